// round 1
// baseline (speedup 1.0000x reference)
#include <cuda_runtime.h>

// Problem constants
#define B_ 4
#define T_ 2048
#define C_ 1024
#define H_ 16
#define D_ 64
#define M_ (B_*T_)   // 8192 rows

// Scratch (device globals: allocation-free per harness rules)
// q,k,v in [B,H,T,D] layout; att output in [B,T,C] layout
__device__ float g_q[(size_t)B_*H_*T_*D_];
__device__ float g_k[(size_t)B_*H_*T_*D_];
__device__ float g_v[(size_t)B_*H_*T_*D_];
__device__ float g_att[(size_t)M_*C_];

// ---------------------------------------------------------------------------
// GEMM: out = A @ W^T + bias,  A:[M,C] row-major, W:[N,C] row-major (N=C here)
// 128x128 block, BK=8, 8x8 per-thread microtile, 256 threads.
// ---------------------------------------------------------------------------

__device__ __forceinline__ void gemm_mainloop_128x128(
    const float* __restrict__ A, const float* __restrict__ W,
    float (*As)[128], float (*Bs)[128],
    float acc[8][8], int mBase, int nBase)
{
    const int tid  = threadIdx.x;
    const int ir   = tid >> 1;          // 0..127
    const int ic   = (tid & 1) * 4;     // 0 or 4
    const int tRow = tid >> 4;          // 0..15
    const int tCol = tid & 15;          // 0..15

    const float* Aptr = A + (size_t)(mBase + ir) * C_ + ic;
    const float* Wptr = W + (size_t)(nBase + ir) * C_ + ic;

    float4 a4 = *(const float4*)(Aptr);
    float4 b4 = *(const float4*)(Wptr);

    for (int k0 = 0; k0 < C_; k0 += 8) {
        As[ic+0][ir] = a4.x; As[ic+1][ir] = a4.y;
        As[ic+2][ir] = a4.z; As[ic+3][ir] = a4.w;
        Bs[ic+0][ir] = b4.x; Bs[ic+1][ir] = b4.y;
        Bs[ic+2][ir] = b4.z; Bs[ic+3][ir] = b4.w;
        __syncthreads();

        if (k0 + 8 < C_) {  // prefetch next K-slab while computing
            a4 = *(const float4*)(Aptr + k0 + 8);
            b4 = *(const float4*)(Wptr + k0 + 8);
        }

        #pragma unroll
        for (int kk = 0; kk < 8; kk++) {
            float rm[8], rn[8];
            *(float4*)(rm)     = *(const float4*)(&As[kk][tRow*8]);
            *(float4*)(rm + 4) = *(const float4*)(&As[kk][tRow*8 + 4]);
            *(float4*)(rn)     = *(const float4*)(&Bs[kk][tCol*8]);
            *(float4*)(rn + 4) = *(const float4*)(&Bs[kk][tCol*8 + 4]);
            #pragma unroll
            for (int i = 0; i < 8; i++)
                #pragma unroll
                for (int j = 0; j < 8; j++)
                    acc[i][j] = fmaf(rm[i], rn[j], acc[i][j]);
        }
        __syncthreads();
    }
}

// QKV projection: grid (C/128=8, M/128=64, 3); z selects q/k/v.
// Writes directly into [B,H,T,D] layout.
__global__ __launch_bounds__(256) void qkv_gemm_kernel(
    const float* __restrict__ x,
    const float* __restrict__ Wq, const float* __restrict__ Wk, const float* __restrict__ Wv,
    const float* __restrict__ bq, const float* __restrict__ bk, const float* __restrict__ bv)
{
    __shared__ float As[8][128];
    __shared__ float Bs[8][128];

    const int z = blockIdx.z;
    const float* W    = (z == 0) ? Wq : (z == 1) ? Wk : Wv;
    const float* bias = (z == 0) ? bq : (z == 1) ? bk : bv;
    float* out        = (z == 0) ? g_q : (z == 1) ? g_k : g_v;

    const int mBase = blockIdx.y * 128;
    const int nBase = blockIdx.x * 128;
    const int tid   = threadIdx.x;
    const int tRow  = tid >> 4;
    const int tCol  = tid & 15;

    float acc[8][8];
    #pragma unroll
    for (int i = 0; i < 8; i++)
        #pragma unroll
        for (int j = 0; j < 8; j++) acc[i][j] = 0.0f;

    gemm_mainloop_128x128(x, W, As, Bs, acc, mBase, nBase);

    const int n0 = nBase + tCol * 8;
    const int h  = n0 >> 6;      // D_=64
    const int d0 = n0 & 63;      // 8 consecutive cols stay within one head
    float bb[8];
    #pragma unroll
    for (int j = 0; j < 8; j++) bb[j] = bias[n0 + j];

    #pragma unroll
    for (int i = 0; i < 8; i++) {
        const int m = mBase + tRow * 8 + i;
        const int b = m >> 11;   // T_=2048
        const int t = m & 2047;
        float* dst = out + (((size_t)(b * H_ + h)) * T_ + t) * D_ + d0;
        float4 o0 = make_float4(acc[i][0]+bb[0], acc[i][1]+bb[1],
                                acc[i][2]+bb[2], acc[i][3]+bb[3]);
        float4 o1 = make_float4(acc[i][4]+bb[4], acc[i][5]+bb[5],
                                acc[i][6]+bb[6], acc[i][7]+bb[7]);
        *(float4*)(dst)     = o0;
        *(float4*)(dst + 4) = o1;
    }
}

// Output projection: out[m, n] = g_att[m, :] . Wp[n, :] + bp[n]
__global__ __launch_bounds__(256) void proj_gemm_kernel(
    const float* __restrict__ Wp, const float* __restrict__ bp,
    float* __restrict__ out)
{
    __shared__ float As[8][128];
    __shared__ float Bs[8][128];

    const int mBase = blockIdx.y * 128;
    const int nBase = blockIdx.x * 128;
    const int tid   = threadIdx.x;
    const int tRow  = tid >> 4;
    const int tCol  = tid & 15;

    float acc[8][8];
    #pragma unroll
    for (int i = 0; i < 8; i++)
        #pragma unroll
        for (int j = 0; j < 8; j++) acc[i][j] = 0.0f;

    gemm_mainloop_128x128(g_att, Wp, As, Bs, acc, mBase, nBase);

    const int n0 = nBase + tCol * 8;
    float bb[8];
    #pragma unroll
    for (int j = 0; j < 8; j++) bb[j] = bp[n0 + j];

    #pragma unroll
    for (int i = 0; i < 8; i++) {
        const int m = mBase + tRow * 8 + i;
        float* dst = out + (size_t)m * C_ + n0;
        float4 o0 = make_float4(acc[i][0]+bb[0], acc[i][1]+bb[1],
                                acc[i][2]+bb[2], acc[i][3]+bb[3]);
        float4 o1 = make_float4(acc[i][4]+bb[4], acc[i][5]+bb[5],
                                acc[i][6]+bb[6], acc[i][7]+bb[7]);
        *(float4*)(dst)     = o0;
        *(float4*)(dst + 4) = o1;
    }
}

// ---------------------------------------------------------------------------
// Flash attention, fp32, causal. One block = one (b,h) x one 64-row Q tile.
// 256 threads as 16x16; each thread owns a 4x4 microtile of S and of O.
// Smem: Qs[64][64] (pre-scaled), Kst[64][68] (d-major, padded), Ps[64][64],
//       Vs[64][64]. 66560 B dynamic.
// ---------------------------------------------------------------------------
#define ATTN_SMEM_BYTES ((64*64 + 64*68 + 64*64 + 64*64) * 4)

__global__ __launch_bounds__(256) void attn_kernel()
{
    extern __shared__ float sm[];
    float* Qs  = sm;                  // [64][64]  q-major
    float* Kst = Qs + 64*64;          // [64][68]  d-major (transposed), pad 4
    float* Ps  = Kst + 64*68;         // [64][64]  q-major
    float* Vs  = Ps + 64*64;          // [64][64]  k-major

    const int bh  = blockIdx.y;                         // 0..63
    const int qi  = (int)gridDim.x - 1 - (int)blockIdx.x; // big tiles first
    const int tid = threadIdx.x;
    const int ty  = tid >> 4;
    const int tx  = tid & 15;

    const size_t base = (size_t)bh * T_ * D_;
    const float* qp  = g_q + base + (size_t)qi * 64 * D_;
    const float* kbp = g_k + base;
    const float* vbp = g_v + base;

    // Load Q tile, pre-scaled by 1/sqrt(D)
    const float scale = 0.125f;  // 1/sqrt(64)
    #pragma unroll
    for (int it = 0; it < 4; it++) {
        int idx = it * 256 + tid;
        int q = idx >> 4, c4 = idx & 15;
        float4 v = *(const float4*)(qp + q * D_ + c4 * 4);
        v.x *= scale; v.y *= scale; v.z *= scale; v.w *= scale;
        *(float4*)(Qs + q * 64 + c4 * 4) = v;
    }

    float m_i[4], l_i[4], acc[4][4];
    #pragma unroll
    for (int i = 0; i < 4; i++) {
        m_i[i] = -1e30f; l_i[i] = 0.0f;
        #pragma unroll
        for (int j = 0; j < 4; j++) acc[i][j] = 0.0f;
    }

    for (int kt = 0; kt <= qi; kt++) {
        __syncthreads();   // Q visible (iter 0); prior PV done before overwrite

        const float* kp = kbp + (size_t)kt * 64 * D_;
        const float* vp = vbp + (size_t)kt * 64 * D_;

        // K tile, transposed into Kst[d][key] (coalesced global reads)
        #pragma unroll
        for (int it = 0; it < 16; it++) {
            int idx = it * 256 + tid;
            int key = idx >> 6, d = idx & 63;
            Kst[d * 68 + key] = kp[key * D_ + d];
        }
        // V tile, straight copy
        #pragma unroll
        for (int it = 0; it < 4; it++) {
            int idx = it * 256 + tid;
            int r = idx >> 4, c4 = idx & 15;
            *(float4*)(Vs + r * 64 + c4 * 4) = *(const float4*)(vp + r * D_ + c4 * 4);
        }
        __syncthreads();

        // S = (Q*scale) K^T  (4x4 per thread), d-unrolled by 4, all LDS.128
        float s[4][4];
        #pragma unroll
        for (int i = 0; i < 4; i++)
            #pragma unroll
            for (int j = 0; j < 4; j++) s[i][j] = 0.0f;

        for (int d = 0; d < 64; d += 4) {
            float rqv[4][4], rkv[4][4];
            #pragma unroll
            for (int i = 0; i < 4; i++) {
                float4 t4 = *(const float4*)(Qs + (ty*4 + i) * 64 + d);
                rqv[i][0]=t4.x; rqv[i][1]=t4.y; rqv[i][2]=t4.z; rqv[i][3]=t4.w;
            }
            #pragma unroll
            for (int c = 0; c < 4; c++) {
                float4 t4 = *(const float4*)(Kst + (d + c) * 68 + tx * 4);
                rkv[c][0]=t4.x; rkv[c][1]=t4.y; rkv[c][2]=t4.z; rkv[c][3]=t4.w;
            }
            #pragma unroll
            for (int i = 0; i < 4; i++)
                #pragma unroll
                for (int c = 0; c < 4; c++)
                    #pragma unroll
                    for (int j = 0; j < 4; j++)
                        s[i][j] = fmaf(rqv[i][c], rkv[c][j], s[i][j]);
        }

        // Causal mask (diagonal tile only; kt<qi tiles are fully visible)
        if (kt == qi) {
            #pragma unroll
            for (int i = 0; i < 4; i++) {
                int qg = ty * 4 + i;
                #pragma unroll
                for (int j = 0; j < 4; j++) {
                    if (tx * 4 + j > qg) s[i][j] = -1e30f;
                }
            }
        }

        // Online softmax per row (row spread over 16 tx lanes; lanes
        // (ty&1)*16+tx so xor 8/4/2/1 stays within the 16-lane row group)
        #pragma unroll
        for (int i = 0; i < 4; i++) {
            float mx = fmaxf(fmaxf(s[i][0], s[i][1]), fmaxf(s[i][2], s[i][3]));
            #pragma unroll
            for (int off = 8; off >= 1; off >>= 1)
                mx = fmaxf(mx, __shfl_xor_sync(0xffffffffu, mx, off));
            float mnew = fmaxf(m_i[i], mx);
            float p[4]; float rs = 0.0f;
            #pragma unroll
            for (int j = 0; j < 4; j++) { p[j] = __expf(s[i][j] - mnew); rs += p[j]; }
            #pragma unroll
            for (int off = 8; off >= 1; off >>= 1)
                rs += __shfl_xor_sync(0xffffffffu, rs, off);
            float alpha = __expf(m_i[i] - mnew);
            l_i[i] = l_i[i] * alpha + rs;
            m_i[i] = mnew;
            #pragma unroll
            for (int j = 0; j < 4; j++) acc[i][j] *= alpha;
            *(float4*)(Ps + (ty*4 + i) * 64 + tx * 4) = make_float4(p[0], p[1], p[2], p[3]);
        }
        __syncthreads();

        // O += P V (kk-unrolled by 4, all LDS.128)
        for (int kk = 0; kk < 64; kk += 4) {
            float rp[4][4], rv[4][4];
            #pragma unroll
            for (int i = 0; i < 4; i++) {
                float4 t4 = *(const float4*)(Ps + (ty*4 + i) * 64 + kk);
                rp[i][0]=t4.x; rp[i][1]=t4.y; rp[i][2]=t4.z; rp[i][3]=t4.w;
            }
            #pragma unroll
            for (int c = 0; c < 4; c++) {
                float4 t4 = *(const float4*)(Vs + (kk + c) * 64 + tx * 4);
                rv[c][0]=t4.x; rv[c][1]=t4.y; rv[c][2]=t4.z; rv[c][3]=t4.w;
            }
            #pragma unroll
            for (int i = 0; i < 4; i++)
                #pragma unroll
                for (int c = 0; c < 4; c++)
                    #pragma unroll
                    for (int j = 0; j < 4; j++)
                        acc[i][j] = fmaf(rp[i][c], rv[c][j], acc[i][j]);
        }
    }

    // Normalize and write to [B,T,C] (c = h*64 + d)
    const int b = bh >> 4;   // H_=16
    const int h = bh & 15;
    #pragma unroll
    for (int i = 0; i < 4; i++) {
        int tq = qi * 64 + ty * 4 + i;
        float inv = 1.0f / l_i[i];
        float4 o = make_float4(acc[i][0]*inv, acc[i][1]*inv,
                               acc[i][2]*inv, acc[i][3]*inv);
        *(float4*)(g_att + ((size_t)(b * T_ + tq)) * C_ + h * 64 + tx * 4) = o;
    }
}

// ---------------------------------------------------------------------------
extern "C" void kernel_launch(void* const* d_in, const int* in_sizes, int n_in,
                              void* d_out, int out_size)
{
    const float* x  = (const float*)d_in[0];
    const float* Wq = (const float*)d_in[1];
    const float* bq = (const float*)d_in[2];
    const float* Wk = (const float*)d_in[3];
    const float* bk = (const float*)d_in[4];
    const float* Wv = (const float*)d_in[5];
    const float* bv = (const float*)d_in[6];
    const float* Wp = (const float*)d_in[7];
    const float* bp = (const float*)d_in[8];
    float* out = (float*)d_out;

    cudaFuncSetAttribute(attn_kernel,
                         cudaFuncAttributeMaxDynamicSharedMemorySize,
                         ATTN_SMEM_BYTES);

    // 1) QKV projections (fused in one launch via z)
    qkv_gemm_kernel<<<dim3(C_/128, M_/128, 3), 256>>>(x, Wq, Wk, Wv, bq, bk, bv);
    // 2) Causal flash attention
    attn_kernel<<<dim3(T_/64, B_*H_), 256, ATTN_SMEM_BYTES>>>();
    // 3) Output projection
    proj_gemm_kernel<<<dim3(C_/128, M_/128), 256>>>(Wp, bp, out);
}

// round 3
// speedup vs baseline: 1.3997x; 1.3997x over previous
#include <cuda_runtime.h>
#include <cuda_bf16.h>
#include <cstdint>

// Problem constants
#define B_ 4
#define T_ 2048
#define C_ 1024
#define H_ 16
#define D_ 64
#define M_ (B_*T_)   // 8192 rows

// ---------------------------------------------------------------------------
// Device scratch (allocation-free)
// ---------------------------------------------------------------------------
__device__ __align__(16) float g_q[(size_t)B_*H_*T_*D_];
__device__ __align__(16) float g_k[(size_t)B_*H_*T_*D_];
__device__ __align__(16) float g_v[(size_t)B_*H_*T_*D_];
// split-bf16 operands
__device__ __align__(16) __nv_bfloat16 g_xhi[(size_t)M_*C_];
__device__ __align__(16) __nv_bfloat16 g_xlo[(size_t)M_*C_];
__device__ __align__(16) __nv_bfloat16 g_whi[(size_t)4*C_*C_];  // q,k,v,p
__device__ __align__(16) __nv_bfloat16 g_wlo[(size_t)4*C_*C_];
__device__ __align__(16) __nv_bfloat16 g_ahi[(size_t)M_*C_];    // attn out hi
__device__ __align__(16) __nv_bfloat16 g_alo[(size_t)M_*C_];    // attn out lo

// ---------------------------------------------------------------------------
// mma.sync helper: D += A(bf16) * B(bf16), m16n8k16, row.col, fp32 accum
// ---------------------------------------------------------------------------
__device__ __forceinline__ void mma16816(float* d, const uint32_t* a, const uint32_t* b) {
    asm volatile(
        "mma.sync.aligned.m16n8k16.row.col.f32.bf16.bf16.f32 "
        "{%0,%1,%2,%3}, {%4,%5,%6,%7}, {%8,%9}, {%0,%1,%2,%3};"
        : "+f"(d[0]), "+f"(d[1]), "+f"(d[2]), "+f"(d[3])
        : "r"(a[0]), "r"(a[1]), "r"(a[2]), "r"(a[3]), "r"(b[0]), "r"(b[1]));
}

// ---------------------------------------------------------------------------
// fp32 -> split bf16 (hi/lo); DST: 0=x, 1..4=weight slot (q,k,v,p)
// ---------------------------------------------------------------------------
template <int DST>
__global__ __launch_bounds__(256) void split_kernel(const float* __restrict__ src, int n8)
{
    int i = blockIdx.x * 256 + threadIdx.x;
    if (i >= n8) return;
    __nv_bfloat16* hi = (DST == 0) ? g_xhi : g_whi + (size_t)(DST - 1) * C_ * C_;
    __nv_bfloat16* lo = (DST == 0) ? g_xlo : g_wlo + (size_t)(DST - 1) * C_ * C_;
    const float4* s4 = (const float4*)src + (size_t)i * 2;
    float4 v0 = s4[0], v1 = s4[1];
    float vs[8] = {v0.x, v0.y, v0.z, v0.w, v1.x, v1.y, v1.z, v1.w};
    union { __nv_bfloat16 h[8]; uint4 u; } HU, LU;
    #pragma unroll
    for (int j = 0; j < 8; j++) {
        __nv_bfloat16 h = __float2bfloat16(vs[j]);
        HU.h[j] = h;
        LU.h[j] = __float2bfloat16(vs[j] - __bfloat162float(h));
    }
    ((uint4*)hi)[i] = HU.u;
    ((uint4*)lo)[i] = LU.u;
}

// ---------------------------------------------------------------------------
// Split-bf16 tensor-core GEMM: out[m,n] = sum_k A[m,k]*W[n,k] + bias[n]
// 128x128 block tile, KC=32 double-buffered, 8 warps @ 32x64 warp tiles.
// MODE 0: A = g_xhi/g_xlo, W slot z (q/k/v), output [B,H,T,D] fp32
// MODE 1: A = g_ahi/g_alo, W slot 3 (p),     output row-major fp32
// ---------------------------------------------------------------------------
#define KC 32
#define SROW 40                            // smem row stride (halves): 80B, conflict-free
#define TILE_H (128 * SROW)                // halves per tensor tile
#define STAGE_H (4 * TILE_H)               // Ahi,Alo,Whi,Wlo
#define GEMM_SMEM (2 * STAGE_H * 2)        // bytes: 81920
#define NCHUNK (C_ / KC)                   // 32

template <int MODE>
__global__ __launch_bounds__(256) void gemm_kernel(
    const float* __restrict__ b0, const float* __restrict__ b1,
    const float* __restrict__ b2, float* __restrict__ out_proj)
{
    extern __shared__ __nv_bfloat16 sh[];
    const int tid  = threadIdx.x;
    const int wid  = tid >> 5;
    const int lane = tid & 31;
    const int wm   = wid & 3;          // warp m index (0..3) -> m offset wm*32
    const int wn   = wid >> 2;         // warp n index (0..1) -> n offset wn*64
    const int g    = lane >> 2;        // fragment group (row within 8)
    const int tg   = lane & 3;         // thread-in-group (k pair)

    const int z     = (MODE == 0) ? blockIdx.z : 3;
    const int mBase = blockIdx.y * 128;
    const int nBase = blockIdx.x * 128;

    const __nv_bfloat16* Ahi = ((MODE == 0) ? g_xhi : g_ahi) + (size_t)mBase * C_;
    const __nv_bfloat16* Alo = ((MODE == 0) ? g_xlo : g_alo) + (size_t)mBase * C_;
    const __nv_bfloat16* Whi = g_whi + (size_t)z * C_ * C_ + (size_t)nBase * C_;
    const __nv_bfloat16* Wlo = g_wlo + (size_t)z * C_ * C_ + (size_t)nBase * C_;
    const __nv_bfloat16* gsrc[4] = {Ahi, Alo, Whi, Wlo};

    // per-thread gmem load coords: 2 rows x 1 j-slot of 8 halves, per tensor
    const int jj = tid & 3;            // 8-half slot within 32-half row
    const int r0 = tid >> 2;           // 0..63
    // smem halves offset within a tile for (r, jj)
    const int so0 = r0 * SROW + jj * 8;
    const int so1 = (r0 + 64) * SROW + jj * 8;

    float acc[2][8][4];
    #pragma unroll
    for (int i = 0; i < 2; i++)
        #pragma unroll
        for (int j = 0; j < 8; j++)
            #pragma unroll
            for (int q = 0; q < 4; q++) acc[i][j][q] = 0.0f;

    // Prologue: load chunk 0 into stage 0
    #pragma unroll
    for (int t = 0; t < 4; t++) {
        const __nv_bfloat16* gp = gsrc[t];
        *(float4*)(sh + t * TILE_H + so0) = *(const float4*)(gp + (size_t)r0 * C_ + jj * 8);
        *(float4*)(sh + t * TILE_H + so1) = *(const float4*)(gp + (size_t)(r0 + 64) * C_ + jj * 8);
    }
    __syncthreads();

    for (int c = 0; c < NCHUNK; c++) {
        const int s = c & 1;
        float4 pf[4][2];
        if (c + 1 < NCHUNK) {
            const int kb = (c + 1) * KC;
            #pragma unroll
            for (int t = 0; t < 4; t++) {
                const __nv_bfloat16* gp = gsrc[t];
                pf[t][0] = *(const float4*)(gp + (size_t)r0 * C_ + kb + jj * 8);
                pf[t][1] = *(const float4*)(gp + (size_t)(r0 + 64) * C_ + kb + jj * 8);
            }
        }

        const __nv_bfloat16* Sah = sh + s * STAGE_H + 0 * TILE_H;
        const __nv_bfloat16* Sal = sh + s * STAGE_H + 1 * TILE_H;
        const __nv_bfloat16* Swh = sh + s * STAGE_H + 2 * TILE_H;
        const __nv_bfloat16* Swl = sh + s * STAGE_H + 3 * TILE_H;

        #pragma unroll
        for (int ks = 0; ks < KC; ks += 16) {
            uint32_t ah[2][4], al[2][4];
            #pragma unroll
            for (int i = 0; i < 2; i++) {
                const int row = wm * 32 + i * 16 + g;
                const int o = row * SROW + ks + tg * 2;
                ah[i][0] = *(const uint32_t*)(Sah + o);
                ah[i][1] = *(const uint32_t*)(Sah + o + 8 * SROW);
                ah[i][2] = *(const uint32_t*)(Sah + o + 8);
                ah[i][3] = *(const uint32_t*)(Sah + o + 8 * SROW + 8);
                al[i][0] = *(const uint32_t*)(Sal + o);
                al[i][1] = *(const uint32_t*)(Sal + o + 8 * SROW);
                al[i][2] = *(const uint32_t*)(Sal + o + 8);
                al[i][3] = *(const uint32_t*)(Sal + o + 8 * SROW + 8);
            }
            uint32_t bh[8][2], bl[8][2];
            #pragma unroll
            for (int j = 0; j < 8; j++) {
                const int row = wn * 64 + j * 8 + g;
                const int o = row * SROW + ks + tg * 2;
                bh[j][0] = *(const uint32_t*)(Swh + o);
                bh[j][1] = *(const uint32_t*)(Swh + o + 8);
                bl[j][0] = *(const uint32_t*)(Swl + o);
                bl[j][1] = *(const uint32_t*)(Swl + o + 8);
            }
            #pragma unroll
            for (int i = 0; i < 2; i++)
                #pragma unroll
                for (int j = 0; j < 8; j++) {
                    mma16816(acc[i][j], ah[i], bh[j]);
                    mma16816(acc[i][j], ah[i], bl[j]);
                    mma16816(acc[i][j], al[i], bh[j]);
                }
        }

        if (c + 1 < NCHUNK) {
            __nv_bfloat16* st = sh + (1 - s) * STAGE_H;
            #pragma unroll
            for (int t = 0; t < 4; t++) {
                *(float4*)(st + t * TILE_H + so0) = pf[t][0];
                *(float4*)(st + t * TILE_H + so1) = pf[t][1];
            }
        }
        __syncthreads();
    }

    // Epilogue
    const float* bias = (MODE == 0) ? ((z == 0) ? b0 : (z == 1) ? b1 : b2) : b0;
    #pragma unroll
    for (int i = 0; i < 2; i++) {
        #pragma unroll
        for (int j = 0; j < 8; j++) {
            const int m0 = mBase + wm * 32 + i * 16 + g;
            const int n  = nBase + wn * 64 + j * 8 + tg * 2;
            const float bx = bias[n], by = bias[n + 1];
            float2 v0 = make_float2(acc[i][j][0] + bx, acc[i][j][1] + by);
            float2 v1 = make_float2(acc[i][j][2] + bx, acc[i][j][3] + by);
            if (MODE == 0) {
                float* outp = (z == 0) ? g_q : (z == 1) ? g_k : g_v;
                const int h = n >> 6, d = n & 63;
                const int b = m0 >> 11, t0 = m0 & (T_ - 1);
                float* base = outp + ((size_t)(b * H_ + h)) * T_ * D_;
                *(float2*)(base + (size_t)t0 * D_ + d)       = v0;
                *(float2*)(base + (size_t)(t0 + 8) * D_ + d) = v1;
            } else {
                *(float2*)(out_proj + (size_t)m0 * C_ + n)       = v0;
                *(float2*)(out_proj + (size_t)(m0 + 8) * C_ + n) = v1;
            }
        }
    }
}

// ---------------------------------------------------------------------------
// Flash attention, fp32, causal. One block = one (b,h) x one 64-row Q tile.
// Epilogue emits bf16 hi/lo splits for the projection GEMM.
// ---------------------------------------------------------------------------
#define ATTN_SMEM_BYTES ((64*64 + 64*68 + 64*64 + 64*64) * 4)

__global__ __launch_bounds__(256) void attn_kernel()
{
    extern __shared__ float sm[];
    float* Qs  = sm;                  // [64][64]  q-major
    float* Kst = Qs + 64*64;          // [64][68]  d-major (transposed), pad 4
    float* Ps  = Kst + 64*68;         // [64][64]  q-major
    float* Vs  = Ps + 64*64;          // [64][64]  k-major

    const int bh  = blockIdx.y;                           // 0..63
    const int qi  = (int)gridDim.x - 1 - (int)blockIdx.x; // big tiles first
    const int tid = threadIdx.x;
    const int ty  = tid >> 4;
    const int tx  = tid & 15;

    const size_t base = (size_t)bh * T_ * D_;
    const float* qp  = g_q + base + (size_t)qi * 64 * D_;
    const float* kbp = g_k + base;
    const float* vbp = g_v + base;

    const float scale = 0.125f;  // 1/sqrt(64)
    #pragma unroll
    for (int it = 0; it < 4; it++) {
        int idx = it * 256 + tid;
        int q = idx >> 4, c4 = idx & 15;
        float4 v = *(const float4*)(qp + q * D_ + c4 * 4);
        v.x *= scale; v.y *= scale; v.z *= scale; v.w *= scale;
        *(float4*)(Qs + q * 64 + c4 * 4) = v;
    }

    float m_i[4], l_i[4], acc[4][4];
    #pragma unroll
    for (int i = 0; i < 4; i++) {
        m_i[i] = -1e30f; l_i[i] = 0.0f;
        #pragma unroll
        for (int j = 0; j < 4; j++) acc[i][j] = 0.0f;
    }

    for (int kt = 0; kt <= qi; kt++) {
        __syncthreads();

        const float* kp = kbp + (size_t)kt * 64 * D_;
        const float* vp = vbp + (size_t)kt * 64 * D_;

        #pragma unroll
        for (int it = 0; it < 16; it++) {
            int idx = it * 256 + tid;
            int key = idx >> 6, d = idx & 63;
            Kst[d * 68 + key] = kp[key * D_ + d];
        }
        #pragma unroll
        for (int it = 0; it < 4; it++) {
            int idx = it * 256 + tid;
            int r = idx >> 4, c4 = idx & 15;
            *(float4*)(Vs + r * 64 + c4 * 4) = *(const float4*)(vp + r * D_ + c4 * 4);
        }
        __syncthreads();

        float s[4][4];
        #pragma unroll
        for (int i = 0; i < 4; i++)
            #pragma unroll
            for (int j = 0; j < 4; j++) s[i][j] = 0.0f;

        for (int d = 0; d < 64; d += 4) {
            float rqv[4][4], rkv[4][4];
            #pragma unroll
            for (int i = 0; i < 4; i++) {
                float4 t4 = *(const float4*)(Qs + (ty*4 + i) * 64 + d);
                rqv[i][0]=t4.x; rqv[i][1]=t4.y; rqv[i][2]=t4.z; rqv[i][3]=t4.w;
            }
            #pragma unroll
            for (int c = 0; c < 4; c++) {
                float4 t4 = *(const float4*)(Kst + (d + c) * 68 + tx * 4);
                rkv[c][0]=t4.x; rkv[c][1]=t4.y; rkv[c][2]=t4.z; rkv[c][3]=t4.w;
            }
            #pragma unroll
            for (int i = 0; i < 4; i++)
                #pragma unroll
                for (int c = 0; c < 4; c++)
                    #pragma unroll
                    for (int j = 0; j < 4; j++)
                        s[i][j] = fmaf(rqv[i][c], rkv[c][j], s[i][j]);
        }

        if (kt == qi) {
            #pragma unroll
            for (int i = 0; i < 4; i++) {
                int qg = ty * 4 + i;
                #pragma unroll
                for (int j = 0; j < 4; j++) {
                    if (tx * 4 + j > qg) s[i][j] = -1e30f;
                }
            }
        }

        #pragma unroll
        for (int i = 0; i < 4; i++) {
            float mx = fmaxf(fmaxf(s[i][0], s[i][1]), fmaxf(s[i][2], s[i][3]));
            #pragma unroll
            for (int off = 8; off >= 1; off >>= 1)
                mx = fmaxf(mx, __shfl_xor_sync(0xffffffffu, mx, off));
            float mnew = fmaxf(m_i[i], mx);
            float p[4]; float rs = 0.0f;
            #pragma unroll
            for (int j = 0; j < 4; j++) { p[j] = __expf(s[i][j] - mnew); rs += p[j]; }
            #pragma unroll
            for (int off = 8; off >= 1; off >>= 1)
                rs += __shfl_xor_sync(0xffffffffu, rs, off);
            float alpha = __expf(m_i[i] - mnew);
            l_i[i] = l_i[i] * alpha + rs;
            m_i[i] = mnew;
            #pragma unroll
            for (int j = 0; j < 4; j++) acc[i][j] *= alpha;
            *(float4*)(Ps + (ty*4 + i) * 64 + tx * 4) = make_float4(p[0], p[1], p[2], p[3]);
        }
        __syncthreads();

        for (int kk = 0; kk < 64; kk += 4) {
            float rp[4][4], rv[4][4];
            #pragma unroll
            for (int i = 0; i < 4; i++) {
                float4 t4 = *(const float4*)(Ps + (ty*4 + i) * 64 + kk);
                rp[i][0]=t4.x; rp[i][1]=t4.y; rp[i][2]=t4.z; rp[i][3]=t4.w;
            }
            #pragma unroll
            for (int c = 0; c < 4; c++) {
                float4 t4 = *(const float4*)(Vs + (kk + c) * 64 + tx * 4);
                rv[c][0]=t4.x; rv[c][1]=t4.y; rv[c][2]=t4.z; rv[c][3]=t4.w;
            }
            #pragma unroll
            for (int i = 0; i < 4; i++)
                #pragma unroll
                for (int c = 0; c < 4; c++)
                    #pragma unroll
                    for (int j = 0; j < 4; j++)
                        acc[i][j] = fmaf(rp[i][c], rv[c][j], acc[i][j]);
        }
    }

    // Epilogue: normalize, write split-bf16 to g_ahi/g_alo ([B,T,C] layout)
    const int b = bh >> 4;
    const int h = bh & 15;
    #pragma unroll
    for (int i = 0; i < 4; i++) {
        int tq = qi * 64 + ty * 4 + i;
        float inv = 1.0f / l_i[i];
        size_t e = ((size_t)(b * T_ + tq)) * C_ + h * 64 + tx * 4;
        union { __nv_bfloat16 hh[4]; uint2 u; } PH, PL;
        #pragma unroll
        for (int j = 0; j < 4; j++) {
            float v = acc[i][j] * inv;
            __nv_bfloat16 hb = __float2bfloat16(v);
            PH.hh[j] = hb;
            PL.hh[j] = __float2bfloat16(v - __bfloat162float(hb));
        }
        *(uint2*)(g_ahi + e) = PH.u;
        *(uint2*)(g_alo + e) = PL.u;
    }
}

// ---------------------------------------------------------------------------
extern "C" void kernel_launch(void* const* d_in, const int* in_sizes, int n_in,
                              void* d_out, int out_size)
{
    const float* x  = (const float*)d_in[0];
    const float* Wq = (const float*)d_in[1];
    const float* bq = (const float*)d_in[2];
    const float* Wk = (const float*)d_in[3];
    const float* bk = (const float*)d_in[4];
    const float* Wv = (const float*)d_in[5];
    const float* bv = (const float*)d_in[6];
    const float* Wp = (const float*)d_in[7];
    const float* bp = (const float*)d_in[8];
    float* out = (float*)d_out;

    cudaFuncSetAttribute(attn_kernel, cudaFuncAttributeMaxDynamicSharedMemorySize,
                         ATTN_SMEM_BYTES);
    cudaFuncSetAttribute(gemm_kernel<0>, cudaFuncAttributeMaxDynamicSharedMemorySize,
                         GEMM_SMEM);
    cudaFuncSetAttribute(gemm_kernel<1>, cudaFuncAttributeMaxDynamicSharedMemorySize,
                         GEMM_SMEM);

    // 1) split fp32 -> bf16 hi/lo
    split_kernel<0><<<(M_*C_/8 + 255)/256, 256>>>(x,  M_*C_/8);
    split_kernel<1><<<(C_*C_/8 + 255)/256, 256>>>(Wq, C_*C_/8);
    split_kernel<2><<<(C_*C_/8 + 255)/256, 256>>>(Wk, C_*C_/8);
    split_kernel<3><<<(C_*C_/8 + 255)/256, 256>>>(Wv, C_*C_/8);
    split_kernel<4><<<(C_*C_/8 + 255)/256, 256>>>(Wp, C_*C_/8);

    // 2) QKV projections on tensor cores (z = q/k/v)
    gemm_kernel<0><<<dim3(C_/128, M_/128, 3), 256, GEMM_SMEM>>>(bq, bk, bv, nullptr);

    // 3) causal flash attention (fp32)
    attn_kernel<<<dim3(T_/64, B_*H_), 256, ATTN_SMEM_BYTES>>>();

    // 4) output projection on tensor cores
    gemm_kernel<1><<<dim3(C_/128, M_/128, 1), 256, GEMM_SMEM>>>(bp, nullptr, nullptr, out);
}

// round 6
// speedup vs baseline: 2.3605x; 1.6865x over previous
#include <cuda_runtime.h>
#include <cuda_bf16.h>
#include <cstdint>

// Problem constants
#define B_ 4
#define T_ 2048
#define C_ 1024
#define H_ 16
#define D_ 64
#define M_ (B_*T_)   // 8192 rows

// ---------------------------------------------------------------------------
// Device scratch (allocation-free)
// ---------------------------------------------------------------------------
// split-bf16 operands
__device__ __align__(16) __nv_bfloat16 g_xhi[(size_t)M_*C_];
__device__ __align__(16) __nv_bfloat16 g_xlo[(size_t)M_*C_];
__device__ __align__(16) __nv_bfloat16 g_whi[(size_t)4*C_*C_];  // q,k,v,p
__device__ __align__(16) __nv_bfloat16 g_wlo[(size_t)4*C_*C_];
// QKV outputs as split bf16; Q pre-scaled by 1/sqrt(D)
__device__ __align__(16) __nv_bfloat16 g_qhi[(size_t)B_*H_*T_*D_];  // [B,H,T,D]
__device__ __align__(16) __nv_bfloat16 g_qlo[(size_t)B_*H_*T_*D_];
__device__ __align__(16) __nv_bfloat16 g_khi[(size_t)B_*H_*T_*D_];  // [B,H,T,D]
__device__ __align__(16) __nv_bfloat16 g_klo[(size_t)B_*H_*T_*D_];
__device__ __align__(16) __nv_bfloat16 g_vthi[(size_t)B_*H_*D_*T_]; // [B,H,D,T]
__device__ __align__(16) __nv_bfloat16 g_vtlo[(size_t)B_*H_*D_*T_];
// attention output (hi/lo) for the projection GEMM, [B,T,C]
__device__ __align__(16) __nv_bfloat16 g_ahi[(size_t)M_*C_];
__device__ __align__(16) __nv_bfloat16 g_alo[(size_t)M_*C_];

// ---------------------------------------------------------------------------
// mma.sync helper: D += A(bf16) * B(bf16), m16n8k16, row.col, fp32 accum
// ---------------------------------------------------------------------------
__device__ __forceinline__ void mma16816(float* d, const uint32_t* a, const uint32_t* b) {
    asm volatile(
        "mma.sync.aligned.m16n8k16.row.col.f32.bf16.bf16.f32 "
        "{%0,%1,%2,%3}, {%4,%5,%6,%7}, {%8,%9}, {%0,%1,%2,%3};"
        : "+f"(d[0]), "+f"(d[1]), "+f"(d[2]), "+f"(d[3])
        : "r"(a[0]), "r"(a[1]), "r"(a[2]), "r"(a[3]), "r"(b[0]), "r"(b[1]));
}

__device__ __forceinline__ uint32_t pack_bf16(float lo, float hi) {
    __nv_bfloat162 p = __float22bfloat162_rn(make_float2(lo, hi));
    return *(uint32_t*)&p;
}

// ---------------------------------------------------------------------------
// fp32 -> split bf16 (hi/lo); DST: 0=x, 1..4=weight slot (q,k,v,p)
// ---------------------------------------------------------------------------
template <int DST>
__global__ __launch_bounds__(256) void split_kernel(const float* __restrict__ src, int n8)
{
    int i = blockIdx.x * 256 + threadIdx.x;
    if (i >= n8) return;
    __nv_bfloat16* hi = (DST == 0) ? g_xhi : g_whi + (size_t)(DST - 1) * C_ * C_;
    __nv_bfloat16* lo = (DST == 0) ? g_xlo : g_wlo + (size_t)(DST - 1) * C_ * C_;
    const float4* s4 = (const float4*)src + (size_t)i * 2;
    float4 v0 = s4[0], v1 = s4[1];
    float vs[8] = {v0.x, v0.y, v0.z, v0.w, v1.x, v1.y, v1.z, v1.w};
    union { __nv_bfloat16 h[8]; uint4 u; } HU, LU;
    #pragma unroll
    for (int j = 0; j < 8; j++) {
        __nv_bfloat16 h = __float2bfloat16(vs[j]);
        HU.h[j] = h;
        LU.h[j] = __float2bfloat16(vs[j] - __bfloat162float(h));
    }
    ((uint4*)hi)[i] = HU.u;
    ((uint4*)lo)[i] = LU.u;
}

// ---------------------------------------------------------------------------
// Split-bf16 tensor-core GEMM: out[m,n] = sum_k A[m,k]*W[n,k] + bias[n]
// 128x128 block tile, KC=32 double-buffered, 8 warps @ 32x64 warp tiles.
// MODE 0: A = x (hi/lo), W slot z (q/k/v); outputs split-bf16:
//         z=0 -> g_q{hi,lo} [B,H,T,D], scaled by 1/8
//         z=1 -> g_k{hi,lo} [B,H,T,D]
//         z=2 -> g_vt{hi,lo} [B,H,D,T] (transposed via smem)
// MODE 1: A = attn out (hi/lo), W slot 3 (p), output fp32 row-major
// ---------------------------------------------------------------------------
#define KC 32
#define SROW 40                            // smem row stride (halves)
#define TILE_H (128 * SROW)
#define STAGE_H (4 * TILE_H)               // Ahi,Alo,Whi,Wlo
#define GEMM_SMEM (2 * STAGE_H * 2)        // 81920 bytes
#define NCHUNK (C_ / KC)                   // 32

template <int MODE>
__global__ __launch_bounds__(256) void gemm_kernel(
    const float* __restrict__ b0, const float* __restrict__ b1,
    const float* __restrict__ b2, float* __restrict__ out_proj)
{
    extern __shared__ __nv_bfloat16 sh[];
    const int tid  = threadIdx.x;
    const int wid  = tid >> 5;
    const int lane = tid & 31;
    const int wm   = wid & 3;
    const int wn   = wid >> 2;
    const int g    = lane >> 2;
    const int tg   = lane & 3;

    const int z     = (MODE == 0) ? blockIdx.z : 3;
    const int mBase = blockIdx.y * 128;
    const int nBase = blockIdx.x * 128;

    const __nv_bfloat16* Ahi = ((MODE == 0) ? g_xhi : g_ahi) + (size_t)mBase * C_;
    const __nv_bfloat16* Alo = ((MODE == 0) ? g_xlo : g_alo) + (size_t)mBase * C_;
    const __nv_bfloat16* Whi = g_whi + (size_t)z * C_ * C_ + (size_t)nBase * C_;
    const __nv_bfloat16* Wlo = g_wlo + (size_t)z * C_ * C_ + (size_t)nBase * C_;
    const __nv_bfloat16* gsrc[4] = {Ahi, Alo, Whi, Wlo};

    const int jj = tid & 3;
    const int r0 = tid >> 2;
    const int so0 = r0 * SROW + jj * 8;
    const int so1 = (r0 + 64) * SROW + jj * 8;

    float acc[2][8][4];
    #pragma unroll
    for (int i = 0; i < 2; i++)
        #pragma unroll
        for (int j = 0; j < 8; j++)
            #pragma unroll
            for (int q = 0; q < 4; q++) acc[i][j][q] = 0.0f;

    #pragma unroll
    for (int t = 0; t < 4; t++) {
        const __nv_bfloat16* gp = gsrc[t];
        *(float4*)(sh + t * TILE_H + so0) = *(const float4*)(gp + (size_t)r0 * C_ + jj * 8);
        *(float4*)(sh + t * TILE_H + so1) = *(const float4*)(gp + (size_t)(r0 + 64) * C_ + jj * 8);
    }
    __syncthreads();

    for (int c = 0; c < NCHUNK; c++) {
        const int s = c & 1;
        float4 pf[4][2];
        if (c + 1 < NCHUNK) {
            const int kb = (c + 1) * KC;
            #pragma unroll
            for (int t = 0; t < 4; t++) {
                const __nv_bfloat16* gp = gsrc[t];
                pf[t][0] = *(const float4*)(gp + (size_t)r0 * C_ + kb + jj * 8);
                pf[t][1] = *(const float4*)(gp + (size_t)(r0 + 64) * C_ + kb + jj * 8);
            }
        }

        const __nv_bfloat16* Sah = sh + s * STAGE_H + 0 * TILE_H;
        const __nv_bfloat16* Sal = sh + s * STAGE_H + 1 * TILE_H;
        const __nv_bfloat16* Swh = sh + s * STAGE_H + 2 * TILE_H;
        const __nv_bfloat16* Swl = sh + s * STAGE_H + 3 * TILE_H;

        #pragma unroll
        for (int ks = 0; ks < KC; ks += 16) {
            uint32_t ah[2][4], al[2][4];
            #pragma unroll
            for (int i = 0; i < 2; i++) {
                const int row = wm * 32 + i * 16 + g;
                const int o = row * SROW + ks + tg * 2;
                ah[i][0] = *(const uint32_t*)(Sah + o);
                ah[i][1] = *(const uint32_t*)(Sah + o + 8 * SROW);
                ah[i][2] = *(const uint32_t*)(Sah + o + 8);
                ah[i][3] = *(const uint32_t*)(Sah + o + 8 * SROW + 8);
                al[i][0] = *(const uint32_t*)(Sal + o);
                al[i][1] = *(const uint32_t*)(Sal + o + 8 * SROW);
                al[i][2] = *(const uint32_t*)(Sal + o + 8);
                al[i][3] = *(const uint32_t*)(Sal + o + 8 * SROW + 8);
            }
            uint32_t bhf[8][2], blf[8][2];
            #pragma unroll
            for (int j = 0; j < 8; j++) {
                const int row = wn * 64 + j * 8 + g;
                const int o = row * SROW + ks + tg * 2;
                bhf[j][0] = *(const uint32_t*)(Swh + o);
                bhf[j][1] = *(const uint32_t*)(Swh + o + 8);
                blf[j][0] = *(const uint32_t*)(Swl + o);
                blf[j][1] = *(const uint32_t*)(Swl + o + 8);
            }
            #pragma unroll
            for (int i = 0; i < 2; i++)
                #pragma unroll
                for (int j = 0; j < 8; j++) {
                    mma16816(acc[i][j], ah[i], bhf[j]);
                    mma16816(acc[i][j], ah[i], blf[j]);
                    mma16816(acc[i][j], al[i], bhf[j]);
                }
        }

        if (c + 1 < NCHUNK) {
            __nv_bfloat16* st = sh + (1 - s) * STAGE_H;
            #pragma unroll
            for (int t = 0; t < 4; t++) {
                *(float4*)(st + t * TILE_H + so0) = pf[t][0];
                *(float4*)(st + t * TILE_H + so1) = pf[t][1];
            }
        }
        __syncthreads();
    }

    // ---------------- Epilogue ----------------
    const float* bias = (MODE == 0) ? ((z == 0) ? b0 : (z == 1) ? b1 : b2) : b0;

    if (MODE == 1) {
        #pragma unroll
        for (int i = 0; i < 2; i++)
            #pragma unroll
            for (int j = 0; j < 8; j++) {
                const int m0 = mBase + wm * 32 + i * 16 + g;
                const int n  = nBase + wn * 64 + j * 8 + tg * 2;
                const float bx = bias[n], by = bias[n + 1];
                *(float2*)(out_proj + (size_t)m0 * C_ + n) =
                    make_float2(acc[i][j][0] + bx, acc[i][j][1] + by);
                *(float2*)(out_proj + (size_t)(m0 + 8) * C_ + n) =
                    make_float2(acc[i][j][2] + bx, acc[i][j][3] + by);
            }
        return;
    }

    // MODE 0: emit split-bf16
    const float qsc = (z == 0) ? 0.125f : 1.0f;
    if (z < 2) {
        __nv_bfloat16* OH = (z == 0) ? g_qhi : g_khi;
        __nv_bfloat16* OL = (z == 0) ? g_qlo : g_klo;
        #pragma unroll
        for (int i = 0; i < 2; i++)
            #pragma unroll
            for (int j = 0; j < 8; j++) {
                const int m0 = mBase + wm * 32 + i * 16 + g;
                const int n  = nBase + wn * 64 + j * 8 + tg * 2;
                const float bx = bias[n], by = bias[n + 1];
                const int h = n >> 6, d = n & 63;
                const int b = m0 >> 11, t0 = m0 & (T_ - 1);
                const size_t base = (((size_t)(b * H_ + h)) * T_ + t0) * D_ + d;
                float v[4] = {(acc[i][j][0] + bx) * qsc, (acc[i][j][1] + by) * qsc,
                              (acc[i][j][2] + bx) * qsc, (acc[i][j][3] + by) * qsc};
                float vh[4], vl[4];
                #pragma unroll
                for (int q = 0; q < 4; q++) {
                    vh[q] = __bfloat162float(__float2bfloat16(v[q]));
                    vl[q] = v[q] - vh[q];
                }
                *(uint32_t*)(OH + base)            = pack_bf16(vh[0], vh[1]);
                *(uint32_t*)(OL + base)            = pack_bf16(vl[0], vl[1]);
                *(uint32_t*)(OH + base + 8 * D_)   = pack_bf16(vh[2], vh[3]);
                *(uint32_t*)(OL + base + 8 * D_)   = pack_bf16(vl[2], vl[3]);
            }
    } else {
        // V: transpose through smem, store [B,H,D,T] coalesced
        __nv_bfloat16* Thi = sh;                // [128][136]
        __nv_bfloat16* Tlo = sh + 128 * 136;
        #pragma unroll
        for (int i = 0; i < 2; i++)
            #pragma unroll
            for (int j = 0; j < 8; j++) {
                const int ml = wm * 32 + i * 16 + g;       // local m (t)
                const int nl = wn * 64 + j * 8 + tg * 2;   // local n (d)
                const int n  = nBase + nl;
                const float bx = bias[n], by = bias[n + 1];
                float v[4] = {acc[i][j][0] + bx, acc[i][j][1] + by,
                              acc[i][j][2] + bx, acc[i][j][3] + by};
                #pragma unroll
                for (int q = 0; q < 4; q++) {
                    const int nn = nl + (q & 1);
                    const int mm = ml + (q >> 1) * 8;
                    __nv_bfloat16 hb = __float2bfloat16(v[q]);
                    Thi[nn * 136 + mm] = hb;
                    Tlo[nn * 136 + mm] = __float2bfloat16(v[q] - __bfloat162float(hb));
                }
            }
        __syncthreads();
        const int b = mBase >> 11, t0 = mBase & (T_ - 1);
        #pragma unroll
        for (int it = 0; it < 8; it++) {
            const int idx = it * 256 + tid;     // 2048 float4 slots
            const int r = idx >> 4, sl = idx & 15;
            const int n = nBase + r;
            const int h = n >> 6, d = n & 63;
            const size_t dst = (((size_t)(b * H_ + h)) * D_ + d) * T_ + t0 + sl * 8;
            *(float4*)(g_vthi + dst) = *(const float4*)(Thi + r * 136 + sl * 8);
            *(float4*)(g_vtlo + dst) = *(const float4*)(Tlo + r * 136 + sl * 8);
        }
    }
}

// ---------------------------------------------------------------------------
// Tensor-core flash attention (split-bf16, causal).
// Block: 128 Q rows, 8 warps x 16 rows; K tiles of 64. D=64.
// Smem: K hi/lo [64][72] + Vt hi/lo [64][72]; Q staged through same buffer.
// ---------------------------------------------------------------------------
#define ASR 72
#define ATTN_SMEM (4 * 64 * ASR * 2)   // 36864 bytes

__global__ __launch_bounds__(256, 1) void attn_kernel()
{
    extern __shared__ __nv_bfloat16 ash[];
    __nv_bfloat16* Kh = ash;                 // [64][72]
    __nv_bfloat16* Kl = ash + 64 * ASR;
    __nv_bfloat16* Vh = ash + 2 * 64 * ASR;  // [64][72]  (d-major)
    __nv_bfloat16* Vl = ash + 3 * 64 * ASR;

    const int bh  = blockIdx.y;
    const int qi  = (int)gridDim.x - 1 - (int)blockIdx.x;  // big tiles first
    const int tid = threadIdx.x;
    const int wid = tid >> 5;
    const int lane = tid & 31;
    const int g = lane >> 2, tg = lane & 3;
    const int wrow = wid * 16;

    const size_t bbase  = (size_t)bh * T_ * D_;   // q,k [B,H,T,D]
    const size_t vtbase = (size_t)bh * D_ * T_;   // vt  [B,H,D,T]

    // Stage Q tile (128x64 halves, hi then lo) into smem, extract fragments
    {
        const __nv_bfloat16* qh = g_qhi + bbase + (size_t)qi * 128 * D_;
        const __nv_bfloat16* ql = g_qlo + bbase + (size_t)qi * 128 * D_;
        #pragma unroll
        for (int it = 0; it < 4; it++) {
            const int idx = it * 256 + tid;       // 1024 slots
            const int r = idx >> 3, sl = idx & 7;
            *(float4*)(ash + r * ASR + sl * 8) = *(const float4*)(qh + (size_t)r * D_ + sl * 8);
            *(float4*)(ash + 128 * ASR + r * ASR + sl * 8) = *(const float4*)(ql + (size_t)r * D_ + sl * 8);
        }
    }
    __syncthreads();

    uint32_t qfh[4][4], qfl[4][4];
    #pragma unroll
    for (int t = 0; t < 4; t++) {
        const int ro = (wrow + g) * ASR + t * 16 + tg * 2;
        qfh[t][0] = *(const uint32_t*)(ash + ro);
        qfh[t][1] = *(const uint32_t*)(ash + ro + 8 * ASR);
        qfh[t][2] = *(const uint32_t*)(ash + ro + 8);
        qfh[t][3] = *(const uint32_t*)(ash + ro + 8 * ASR + 8);
        qfl[t][0] = *(const uint32_t*)(ash + 128 * ASR + ro);
        qfl[t][1] = *(const uint32_t*)(ash + 128 * ASR + ro + 8 * ASR);
        qfl[t][2] = *(const uint32_t*)(ash + 128 * ASR + ro + 8);
        qfl[t][3] = *(const uint32_t*)(ash + 128 * ASR + ro + 8 * ASR + 8);
    }

    float m_i[2] = {-1e30f, -1e30f};
    float l_i[2] = {0.0f, 0.0f};
    float oacc[8][4];
    #pragma unroll
    for (int j = 0; j < 8; j++)
        #pragma unroll
        for (int q = 0; q < 4; q++) oacc[j][q] = 0.0f;

    const int qr0 = qi * 128 + wrow + g;   // row for acc[.][0..1]; +8 for [2..3]
    const int nkt = 2 * qi + 2;

    for (int kt = 0; kt < nkt; kt++) {
        __syncthreads();
        // Load K (row-major [key][d]) and Vt ([d][key]) tiles, hi+lo
        #pragma unroll
        for (int it = 0; it < 2; it++) {
            const int idx = it * 256 + tid;    // 512 slots
            const int r = idx >> 3, sl = idx & 7;
            const size_t ko = (size_t)(kt * 64 + r) * D_ + sl * 8;
            *(float4*)(Kh + r * ASR + sl * 8) = *(const float4*)(g_khi + bbase + ko);
            *(float4*)(Kl + r * ASR + sl * 8) = *(const float4*)(g_klo + bbase + ko);
            const size_t vo = (size_t)r * T_ + kt * 64 + sl * 8;
            *(float4*)(Vh + r * ASR + sl * 8) = *(const float4*)(g_vthi + vtbase + vo);
            *(float4*)(Vl + r * ASR + sl * 8) = *(const float4*)(g_vtlo + vtbase + vo);
        }
        __syncthreads();

        // S = Q K^T (split-bf16, 3 passes)
        float sacc[8][4];
        #pragma unroll
        for (int j = 0; j < 8; j++)
            #pragma unroll
            for (int q = 0; q < 4; q++) sacc[j][q] = 0.0f;

        #pragma unroll
        for (int t = 0; t < 4; t++) {
            #pragma unroll
            for (int j = 0; j < 8; j++) {
                const int bo = (j * 8 + g) * ASR + t * 16 + tg * 2;
                uint32_t bhf[2] = {*(const uint32_t*)(Kh + bo), *(const uint32_t*)(Kh + bo + 8)};
                uint32_t blf[2] = {*(const uint32_t*)(Kl + bo), *(const uint32_t*)(Kl + bo + 8)};
                mma16816(sacc[j], qfh[t], bhf);
                mma16816(sacc[j], qfh[t], blf);
                mma16816(sacc[j], qfl[t], bhf);
            }
        }

        // Causal mask (only tiles that can cross the diagonal)
        if (kt * 64 + 63 > qr0) {
            #pragma unroll
            for (int j = 0; j < 8; j++) {
                const int kc = kt * 64 + j * 8 + tg * 2;
                if (kc     > qr0)     sacc[j][0] = -1e30f;
                if (kc + 1 > qr0)     sacc[j][1] = -1e30f;
                if (kc     > qr0 + 8) sacc[j][2] = -1e30f;
                if (kc + 1 > qr0 + 8) sacc[j][3] = -1e30f;
            }
        }

        // Online softmax (2 rows per thread; quad-wide reductions)
        float mx0 = -1e30f, mx1 = -1e30f;
        #pragma unroll
        for (int j = 0; j < 8; j++) {
            mx0 = fmaxf(mx0, fmaxf(sacc[j][0], sacc[j][1]));
            mx1 = fmaxf(mx1, fmaxf(sacc[j][2], sacc[j][3]));
        }
        mx0 = fmaxf(mx0, __shfl_xor_sync(0xffffffffu, mx0, 1));
        mx0 = fmaxf(mx0, __shfl_xor_sync(0xffffffffu, mx0, 2));
        mx1 = fmaxf(mx1, __shfl_xor_sync(0xffffffffu, mx1, 1));
        mx1 = fmaxf(mx1, __shfl_xor_sync(0xffffffffu, mx1, 2));
        const float mn0 = fmaxf(m_i[0], mx0);
        const float mn1 = fmaxf(m_i[1], mx1);
        const float a0 = __expf(m_i[0] - mn0);
        const float a1 = __expf(m_i[1] - mn1);
        m_i[0] = mn0; m_i[1] = mn1;

        float rs0 = 0.0f, rs1 = 0.0f;
        uint32_t pfh[4][4], pfl[4][4];
        #pragma unroll
        for (int j = 0; j < 8; j++) {
            const float p0 = __expf(sacc[j][0] - mn0);
            const float p1 = __expf(sacc[j][1] - mn0);
            const float p2 = __expf(sacc[j][2] - mn1);
            const float p3 = __expf(sacc[j][3] - mn1);
            rs0 += p0 + p1; rs1 += p2 + p3;
            float h0 = __bfloat162float(__float2bfloat16(p0));
            float h1 = __bfloat162float(__float2bfloat16(p1));
            float h2 = __bfloat162float(__float2bfloat16(p2));
            float h3 = __bfloat162float(__float2bfloat16(p3));
            const int t = j >> 1;
            const int o = (j & 1) * 2;   // j even -> a0/a1 ; j odd -> a2/a3
            pfh[t][o + 0] = pack_bf16(h0, h1);
            pfh[t][o + 1] = pack_bf16(h2, h3);
            pfl[t][o + 0] = pack_bf16(p0 - h0, p1 - h1);
            pfl[t][o + 1] = pack_bf16(p2 - h2, p3 - h3);
        }
        rs0 += __shfl_xor_sync(0xffffffffu, rs0, 1);
        rs0 += __shfl_xor_sync(0xffffffffu, rs0, 2);
        rs1 += __shfl_xor_sync(0xffffffffu, rs1, 1);
        rs1 += __shfl_xor_sync(0xffffffffu, rs1, 2);
        l_i[0] = l_i[0] * a0 + rs0;
        l_i[1] = l_i[1] * a1 + rs1;

        #pragma unroll
        for (int j = 0; j < 8; j++) {
            oacc[j][0] *= a0; oacc[j][1] *= a0;
            oacc[j][2] *= a1; oacc[j][3] *= a1;
        }

        // O += P V (split-bf16, 3 passes); B frags from Vt [d][key]
        #pragma unroll
        for (int t = 0; t < 4; t++) {
            #pragma unroll
            for (int j = 0; j < 8; j++) {
                const int bo = (j * 8 + g) * ASR + t * 16 + tg * 2;
                uint32_t bvh[2] = {*(const uint32_t*)(Vh + bo), *(const uint32_t*)(Vh + bo + 8)};
                uint32_t bvl[2] = {*(const uint32_t*)(Vl + bo), *(const uint32_t*)(Vl + bo + 8)};
                mma16816(oacc[j], pfh[t], bvh);
                mma16816(oacc[j], pfh[t], bvl);
                mma16816(oacc[j], pfl[t], bvh);
            }
        }
    }

    // Epilogue: normalize; emit split-bf16 into [B,T,C]
    const float inv0 = 1.0f / l_i[0];
    const float inv1 = 1.0f / l_i[1];
    const int b = bh >> 4, h = bh & 15;
    const int trow = qi * 128 + wrow + g;
    #pragma unroll
    for (int j = 0; j < 8; j++) {
        const int d = j * 8 + tg * 2;
        const size_t e0 = ((size_t)(b * T_ + trow)) * C_ + h * 64 + d;
        const size_t e1 = ((size_t)(b * T_ + trow + 8)) * C_ + h * 64 + d;
        float v0 = oacc[j][0] * inv0, v1 = oacc[j][1] * inv0;
        float v2 = oacc[j][2] * inv1, v3 = oacc[j][3] * inv1;
        float h0 = __bfloat162float(__float2bfloat16(v0));
        float h1 = __bfloat162float(__float2bfloat16(v1));
        float h2 = __bfloat162float(__float2bfloat16(v2));
        float h3 = __bfloat162float(__float2bfloat16(v3));
        *(uint32_t*)(g_ahi + e0) = pack_bf16(h0, h1);
        *(uint32_t*)(g_alo + e0) = pack_bf16(v0 - h0, v1 - h1);
        *(uint32_t*)(g_ahi + e1) = pack_bf16(h2, h3);
        *(uint32_t*)(g_alo + e1) = pack_bf16(v2 - h2, v3 - h3);
    }
}

// ---------------------------------------------------------------------------
extern "C" void kernel_launch(void* const* d_in, const int* in_sizes, int n_in,
                              void* d_out, int out_size)
{
    const float* x  = (const float*)d_in[0];
    const float* Wq = (const float*)d_in[1];
    const float* bq = (const float*)d_in[2];
    const float* Wk = (const float*)d_in[3];
    const float* bk = (const float*)d_in[4];
    const float* Wv = (const float*)d_in[5];
    const float* bv = (const float*)d_in[6];
    const float* Wp = (const float*)d_in[7];
    const float* bp = (const float*)d_in[8];
    float* out = (float*)d_out;

    cudaFuncSetAttribute(attn_kernel, cudaFuncAttributeMaxDynamicSharedMemorySize,
                         ATTN_SMEM);
    cudaFuncSetAttribute(gemm_kernel<0>, cudaFuncAttributeMaxDynamicSharedMemorySize,
                         GEMM_SMEM);
    cudaFuncSetAttribute(gemm_kernel<1>, cudaFuncAttributeMaxDynamicSharedMemorySize,
                         GEMM_SMEM);

    // 1) split fp32 -> bf16 hi/lo
    split_kernel<0><<<(M_*C_/8 + 255)/256, 256>>>(x,  M_*C_/8);
    split_kernel<1><<<(C_*C_/8 + 255)/256, 256>>>(Wq, C_*C_/8);
    split_kernel<2><<<(C_*C_/8 + 255)/256, 256>>>(Wk, C_*C_/8);
    split_kernel<3><<<(C_*C_/8 + 255)/256, 256>>>(Wv, C_*C_/8);
    split_kernel<4><<<(C_*C_/8 + 255)/256, 256>>>(Wp, C_*C_/8);

    // 2) QKV projections (tensor cores, split-bf16 outputs)
    gemm_kernel<0><<<dim3(C_/128, M_/128, 3), 256, GEMM_SMEM>>>(bq, bk, bv, nullptr);

    // 3) causal flash attention (tensor cores)
    attn_kernel<<<dim3(T_/128, B_*H_), 256, ATTN_SMEM>>>();

    // 4) output projection (tensor cores)
    gemm_kernel<1><<<dim3(C_/128, M_/128, 1), 256, GEMM_SMEM>>>(bp, nullptr, nullptr, out);
}

// round 7
// speedup vs baseline: 2.7203x; 1.1524x over previous
#include <cuda_runtime.h>
#include <cuda_bf16.h>
#include <cstdint>

// Problem constants
#define B_ 4
#define T_ 2048
#define C_ 1024
#define H_ 16
#define D_ 64
#define M_ (B_*T_)   // 8192 rows

// ---------------------------------------------------------------------------
// Device scratch (allocation-free)
// ---------------------------------------------------------------------------
__device__ __align__(16) __nv_bfloat16 g_xhi[(size_t)M_*C_];
__device__ __align__(16) __nv_bfloat16 g_xlo[(size_t)M_*C_];
__device__ __align__(16) __nv_bfloat16 g_whi[(size_t)4*C_*C_];  // q,k,v,p
__device__ __align__(16) __nv_bfloat16 g_wlo[(size_t)4*C_*C_];
__device__ __align__(16) __nv_bfloat16 g_qhi[(size_t)B_*H_*T_*D_];  // [B,H,T,D]
__device__ __align__(16) __nv_bfloat16 g_qlo[(size_t)B_*H_*T_*D_];
__device__ __align__(16) __nv_bfloat16 g_khi[(size_t)B_*H_*T_*D_];  // [B,H,T,D]
__device__ __align__(16) __nv_bfloat16 g_klo[(size_t)B_*H_*T_*D_];
__device__ __align__(16) __nv_bfloat16 g_vthi[(size_t)B_*H_*D_*T_]; // [B,H,D,T]
__device__ __align__(16) __nv_bfloat16 g_vtlo[(size_t)B_*H_*D_*T_];
__device__ __align__(16) __nv_bfloat16 g_ahi[(size_t)M_*C_];        // attn out
__device__ __align__(16) __nv_bfloat16 g_alo[(size_t)M_*C_];

// ---------------------------------------------------------------------------
// PTX helpers
// ---------------------------------------------------------------------------
__device__ __forceinline__ void mma16816(float* d, const uint32_t* a, const uint32_t* b) {
    asm volatile(
        "mma.sync.aligned.m16n8k16.row.col.f32.bf16.bf16.f32 "
        "{%0,%1,%2,%3}, {%4,%5,%6,%7}, {%8,%9}, {%0,%1,%2,%3};"
        : "+f"(d[0]), "+f"(d[1]), "+f"(d[2]), "+f"(d[3])
        : "r"(a[0]), "r"(a[1]), "r"(a[2]), "r"(a[3]), "r"(b[0]), "r"(b[1]));
}

__device__ __forceinline__ void ldsm4(uint32_t* r, uint32_t addr) {
    asm volatile("ldmatrix.sync.aligned.m8n8.x4.shared.b16 {%0,%1,%2,%3}, [%4];"
                 : "=r"(r[0]), "=r"(r[1]), "=r"(r[2]), "=r"(r[3]) : "r"(addr));
}

__device__ __forceinline__ uint32_t sptr(const void* p) {
    return (uint32_t)__cvta_generic_to_shared(p);
}

__device__ __forceinline__ void cpa16(uint32_t s, const void* g) {
    asm volatile("cp.async.cg.shared.global [%0], [%1], 16;" :: "r"(s), "l"(g));
}
#define CP_COMMIT asm volatile("cp.async.commit_group;" ::: "memory")
#define CP_WAIT0  asm volatile("cp.async.wait_group 0;" ::: "memory")

__device__ __forceinline__ uint32_t pack_bf16(float lo, float hi) {
    __nv_bfloat162 p = __float22bfloat162_rn(make_float2(lo, hi));
    return *(uint32_t*)&p;
}

// ---------------------------------------------------------------------------
// fp32 -> split bf16 (hi/lo); DST: 0=x, 1..4=weight slot (q,k,v,p)
// ---------------------------------------------------------------------------
template <int DST>
__global__ __launch_bounds__(256) void split_kernel(const float* __restrict__ src, int n8)
{
    int i = blockIdx.x * 256 + threadIdx.x;
    if (i >= n8) return;
    __nv_bfloat16* hi = (DST == 0) ? g_xhi : g_whi + (size_t)(DST - 1) * C_ * C_;
    __nv_bfloat16* lo = (DST == 0) ? g_xlo : g_wlo + (size_t)(DST - 1) * C_ * C_;
    const float4* s4 = (const float4*)src + (size_t)i * 2;
    float4 v0 = s4[0], v1 = s4[1];
    float vs[8] = {v0.x, v0.y, v0.z, v0.w, v1.x, v1.y, v1.z, v1.w};
    union { __nv_bfloat16 h[8]; uint4 u; } HU, LU;
    #pragma unroll
    for (int j = 0; j < 8; j++) {
        __nv_bfloat16 h = __float2bfloat16(vs[j]);
        HU.h[j] = h;
        LU.h[j] = __float2bfloat16(vs[j] - __bfloat162float(h));
    }
    ((uint4*)hi)[i] = HU.u;
    ((uint4*)lo)[i] = LU.u;
}

// ---------------------------------------------------------------------------
// Split-bf16 tensor-core GEMM (ldmatrix + cp.async double-buffer)
// 128x128 block tile, KC=32, 8 warps @ 32x64 warp tiles.
// ---------------------------------------------------------------------------
#define KC 32
#define SROW 40                            // smem row stride (halves), 80B
#define TILE_H (128 * SROW)
#define STAGE_H (4 * TILE_H)               // Ahi,Alo,Whi,Wlo
#define TILE_B (TILE_H * 2)
#define STAGE_B (STAGE_H * 2)
#define GEMM_SMEM (2 * STAGE_B)            // 81920 bytes
#define NCHUNK (C_ / KC)                   // 32

template <int MODE>
__global__ __launch_bounds__(256) void gemm_kernel(
    const float* __restrict__ b0, const float* __restrict__ b1,
    const float* __restrict__ b2, float* __restrict__ out_proj)
{
    extern __shared__ __nv_bfloat16 sh[];
    const int tid  = threadIdx.x;
    const int wid  = tid >> 5;
    const int lane = tid & 31;
    const int wm   = wid & 3;
    const int wn   = wid >> 2;
    const int g    = lane >> 2;
    const int tg   = lane & 3;

    const int z     = (MODE == 0) ? blockIdx.z : 3;
    const int mBase = blockIdx.y * 128;
    const int nBase = blockIdx.x * 128;

    const __nv_bfloat16* Ahi = ((MODE == 0) ? g_xhi : g_ahi) + (size_t)mBase * C_;
    const __nv_bfloat16* Alo = ((MODE == 0) ? g_xlo : g_alo) + (size_t)mBase * C_;
    const __nv_bfloat16* Whi = g_whi + (size_t)z * C_ * C_ + (size_t)nBase * C_;
    const __nv_bfloat16* Wlo = g_wlo + (size_t)z * C_ * C_ + (size_t)nBase * C_;
    const __nv_bfloat16* gsrc[4] = {Ahi, Alo, Whi, Wlo};

    // cp.async dst coords: 2 rows x 8 halves per tensor per thread
    const int jj = tid & 3;
    const int r0 = tid >> 2;
    const int so0 = (r0 * SROW + jj * 8) * 2;          // bytes
    const int so1 = ((r0 + 64) * SROW + jj * 8) * 2;

    // ldmatrix lane->address mapping
    const int laneA_row = (lane & 7) + ((lane >> 3) & 1) * 8;  // tiles: a0,a1 rows; a2,a3 k+8
    const int laneA_k   = ((lane >> 4) & 1) * 8;
    const int laneB_row = (lane & 7) + ((lane >> 4) & 1) * 8;  // pair of n-tiles
    const int laneB_k   = ((lane >> 3) & 1) * 8;

    const uint32_t sp0 = sptr(sh);
    const uint32_t aHb = sp0 + ((wm * 32 + laneA_row) * SROW + laneA_k) * 2;
    const uint32_t aLb = aHb + TILE_B;
    const uint32_t bHb = sp0 + 2 * TILE_B + ((wn * 64 + laneB_row) * SROW + laneB_k) * 2;
    const uint32_t bLb = bHb + TILE_B;

    float acc[2][8][4];
    #pragma unroll
    for (int i = 0; i < 2; i++)
        #pragma unroll
        for (int j = 0; j < 8; j++)
            #pragma unroll
            for (int q = 0; q < 4; q++) acc[i][j][q] = 0.0f;

    // prologue: chunk 0 -> stage 0
    #pragma unroll
    for (int t = 0; t < 4; t++) {
        cpa16(sp0 + t * TILE_B + so0, gsrc[t] + (size_t)r0 * C_ + jj * 8);
        cpa16(sp0 + t * TILE_B + so1, gsrc[t] + (size_t)(r0 + 64) * C_ + jj * 8);
    }
    CP_COMMIT;

    for (int c = 0; c < NCHUNK; c++) {
        const int s = c & 1;
        CP_WAIT0;
        __syncthreads();   // stage s ready; all warps done reading stage 1-s

        if (c + 1 < NCHUNK) {
            const int kb = (c + 1) * KC;
            const uint32_t st = sp0 + (uint32_t)(1 - s) * STAGE_B;
            #pragma unroll
            for (int t = 0; t < 4; t++) {
                cpa16(st + t * TILE_B + so0, gsrc[t] + (size_t)r0 * C_ + kb + jj * 8);
                cpa16(st + t * TILE_B + so1, gsrc[t] + (size_t)(r0 + 64) * C_ + kb + jj * 8);
            }
            CP_COMMIT;
        }

        const uint32_t off = (uint32_t)s * STAGE_B;
        #pragma unroll
        for (int ks = 0; ks < KC; ks += 16) {
            uint32_t ah[2][4], al[2][4], bh4[16], bl4[16];
            #pragma unroll
            for (int i = 0; i < 2; i++) {
                ldsm4(ah[i], aHb + off + (i * 16 * SROW + ks) * 2);
                ldsm4(al[i], aLb + off + (i * 16 * SROW + ks) * 2);
            }
            #pragma unroll
            for (int jp = 0; jp < 4; jp++) {
                ldsm4(&bh4[jp * 4], bHb + off + (jp * 16 * SROW + ks) * 2);
                ldsm4(&bl4[jp * 4], bLb + off + (jp * 16 * SROW + ks) * 2);
            }
            #pragma unroll
            for (int i = 0; i < 2; i++)
                #pragma unroll
                for (int j = 0; j < 8; j++) {
                    const uint32_t* bh = &bh4[(j >> 1) * 4 + (j & 1) * 2];
                    const uint32_t* bl = &bl4[(j >> 1) * 4 + (j & 1) * 2];
                    mma16816(acc[i][j], ah[i], bh);
                    mma16816(acc[i][j], ah[i], bl);
                    mma16816(acc[i][j], al[i], bh);
                }
        }
    }

    // ---------------- Epilogue ----------------
    const float* bias = (MODE == 0) ? ((z == 0) ? b0 : (z == 1) ? b1 : b2) : b0;

    if (MODE == 1) {
        #pragma unroll
        for (int i = 0; i < 2; i++)
            #pragma unroll
            for (int j = 0; j < 8; j++) {
                const int m0 = mBase + wm * 32 + i * 16 + g;
                const int n  = nBase + wn * 64 + j * 8 + tg * 2;
                const float bx = bias[n], by = bias[n + 1];
                *(float2*)(out_proj + (size_t)m0 * C_ + n) =
                    make_float2(acc[i][j][0] + bx, acc[i][j][1] + by);
                *(float2*)(out_proj + (size_t)(m0 + 8) * C_ + n) =
                    make_float2(acc[i][j][2] + bx, acc[i][j][3] + by);
            }
        return;
    }

    const float qsc = (z == 0) ? 0.125f : 1.0f;
    if (z < 2) {
        __nv_bfloat16* OH = (z == 0) ? g_qhi : g_khi;
        __nv_bfloat16* OL = (z == 0) ? g_qlo : g_klo;
        #pragma unroll
        for (int i = 0; i < 2; i++)
            #pragma unroll
            for (int j = 0; j < 8; j++) {
                const int m0 = mBase + wm * 32 + i * 16 + g;
                const int n  = nBase + wn * 64 + j * 8 + tg * 2;
                const float bx = bias[n], by = bias[n + 1];
                const int h = n >> 6, d = n & 63;
                const int b = m0 >> 11, t0 = m0 & (T_ - 1);
                const size_t base = (((size_t)(b * H_ + h)) * T_ + t0) * D_ + d;
                float v[4] = {(acc[i][j][0] + bx) * qsc, (acc[i][j][1] + by) * qsc,
                              (acc[i][j][2] + bx) * qsc, (acc[i][j][3] + by) * qsc};
                float vh[4], vl[4];
                #pragma unroll
                for (int q = 0; q < 4; q++) {
                    vh[q] = __bfloat162float(__float2bfloat16(v[q]));
                    vl[q] = v[q] - vh[q];
                }
                *(uint32_t*)(OH + base)          = pack_bf16(vh[0], vh[1]);
                *(uint32_t*)(OL + base)          = pack_bf16(vl[0], vl[1]);
                *(uint32_t*)(OH + base + 8 * D_) = pack_bf16(vh[2], vh[3]);
                *(uint32_t*)(OL + base + 8 * D_) = pack_bf16(vl[2], vl[3]);
            }
    } else {
        // V: transpose through smem, store [B,H,D,T] coalesced
        __syncthreads();   // all warps done with mainloop smem
        __nv_bfloat16* Thi = sh;                // [128][136]
        __nv_bfloat16* Tlo = sh + 128 * 136;
        #pragma unroll
        for (int i = 0; i < 2; i++)
            #pragma unroll
            for (int j = 0; j < 8; j++) {
                const int ml = wm * 32 + i * 16 + g;       // local m (t)
                const int nl = wn * 64 + j * 8 + tg * 2;   // local n (d)
                const int n  = nBase + nl;
                const float bx = bias[n], by = bias[n + 1];
                float v[4] = {acc[i][j][0] + bx, acc[i][j][1] + by,
                              acc[i][j][2] + bx, acc[i][j][3] + by};
                #pragma unroll
                for (int q = 0; q < 4; q++) {
                    const int nn = nl + (q & 1);
                    const int mm = ml + (q >> 1) * 8;
                    __nv_bfloat16 hb = __float2bfloat16(v[q]);
                    Thi[nn * 136 + mm] = hb;
                    Tlo[nn * 136 + mm] = __float2bfloat16(v[q] - __bfloat162float(hb));
                }
            }
        __syncthreads();
        const int b = mBase >> 11, t0 = mBase & (T_ - 1);
        #pragma unroll
        for (int it = 0; it < 8; it++) {
            const int idx = it * 256 + tid;     // 2048 float4 slots
            const int r = idx >> 4, sl = idx & 15;
            const int n = nBase + r;
            const int h = n >> 6, d = n & 63;
            const size_t dst = (((size_t)(b * H_ + h)) * D_ + d) * T_ + t0 + sl * 8;
            *(float4*)(g_vthi + dst) = *(const float4*)(Thi + r * 136 + sl * 8);
            *(float4*)(g_vtlo + dst) = *(const float4*)(Tlo + r * 136 + sl * 8);
        }
    }
}

// ---------------------------------------------------------------------------
// Tensor-core flash attention (split-bf16, causal), ldmatrix + cp.async
// double-buffered K/V tiles. Block: 128 Q rows, 8 warps x 16 rows; K tile 64.
// ---------------------------------------------------------------------------
#define ASR 72
#define ATILE_H (64 * ASR)             // halves per tensor tile
#define ASTAGE_H (4 * ATILE_H)         // Kh,Kl,Vh,Vl
#define ATILE_B (ATILE_H * 2)
#define ASTAGE_B (ASTAGE_H * 2)        // 36864 bytes
#define ATTN_SMEM (2 * ASTAGE_B)       // 73728 bytes

__global__ __launch_bounds__(256, 1) void attn_kernel()
{
    extern __shared__ __nv_bfloat16 ash[];

    const int bh  = blockIdx.y;
    const int qi  = (int)gridDim.x - 1 - (int)blockIdx.x;  // big tiles first
    const int tid = threadIdx.x;
    const int wid = tid >> 5;
    const int lane = tid & 31;
    const int g = lane >> 2, tg = lane & 3;
    const int wrow = wid * 16;

    const size_t bbase  = (size_t)bh * T_ * D_;   // q,k [B,H,T,D]
    const size_t vtbase = (size_t)bh * D_ * T_;   // vt  [B,H,D,T]

    const uint32_t sp0 = sptr(ash);
    const int laneB_row = (lane & 7) + ((lane >> 4) & 1) * 8;
    const int laneB_k   = ((lane >> 3) & 1) * 8;
    const uint32_t kHb = sp0 + (laneB_row * ASR + laneB_k) * 2;
    const uint32_t kLb = kHb + ATILE_B;
    const uint32_t vHb = kHb + 2 * ATILE_B;
    const uint32_t vLb = kHb + 3 * ATILE_B;

    // Stage Q tile into smem (stage-0 region), extract fragments
    {
        const __nv_bfloat16* qh = g_qhi + bbase + (size_t)qi * 128 * D_;
        const __nv_bfloat16* ql = g_qlo + bbase + (size_t)qi * 128 * D_;
        #pragma unroll
        for (int it = 0; it < 4; it++) {
            const int idx = it * 256 + tid;       // 1024 slots
            const int r = idx >> 3, sl = idx & 7;
            *(float4*)(ash + r * ASR + sl * 8) = *(const float4*)(qh + (size_t)r * D_ + sl * 8);
            *(float4*)(ash + 128 * ASR + r * ASR + sl * 8) = *(const float4*)(ql + (size_t)r * D_ + sl * 8);
        }
    }
    __syncthreads();

    uint32_t qfh[4][4], qfl[4][4];
    {
        const int laneA_row = (lane & 7) + ((lane >> 3) & 1) * 8;
        const int laneA_k   = ((lane >> 4) & 1) * 8;
        const uint32_t qb = sp0 + ((wrow + laneA_row) * ASR + laneA_k) * 2;
        #pragma unroll
        for (int t = 0; t < 4; t++) {
            ldsm4(qfh[t], qb + (t * 16) * 2);
            ldsm4(qfl[t], qb + (128 * ASR + t * 16) * 2);
        }
    }
    __syncthreads();   // Q fragments extracted; smem free for K/V stages

    float m_i[2] = {-1e30f, -1e30f};
    float l_i[2] = {0.0f, 0.0f};
    float oacc[8][4];
    #pragma unroll
    for (int j = 0; j < 8; j++)
        #pragma unroll
        for (int q = 0; q < 4; q++) oacc[j][q] = 0.0f;

    const int qr0 = qi * 128 + wrow + g;
    const int nkt = 2 * qi + 2;

    // prologue: tile 0 -> stage 0
    #pragma unroll
    for (int it = 0; it < 2; it++) {
        const int idx = it * 256 + tid;    // 512 slots
        const int r = idx >> 3, sl = idx & 7;
        const uint32_t doff = (uint32_t)(r * ASR + sl * 8) * 2;
        cpa16(sp0 + doff,              g_khi  + bbase  + (size_t)r * D_ + sl * 8);
        cpa16(sp0 + doff + ATILE_B,    g_klo  + bbase  + (size_t)r * D_ + sl * 8);
        cpa16(sp0 + doff + 2*ATILE_B,  g_vthi + vtbase + (size_t)r * T_ + sl * 8);
        cpa16(sp0 + doff + 3*ATILE_B,  g_vtlo + vtbase + (size_t)r * T_ + sl * 8);
    }
    CP_COMMIT;

    for (int kt = 0; kt < nkt; kt++) {
        const int s = kt & 1;
        CP_WAIT0;
        __syncthreads();   // stage s ready; everyone done reading stage 1-s

        if (kt + 1 < nkt) {
            const int kb = (kt + 1) * 64;
            const uint32_t st = sp0 + (uint32_t)(1 - s) * ASTAGE_B;
            #pragma unroll
            for (int it = 0; it < 2; it++) {
                const int idx = it * 256 + tid;
                const int r = idx >> 3, sl = idx & 7;
                const uint32_t doff = (uint32_t)(r * ASR + sl * 8) * 2;
                cpa16(st + doff,              g_khi  + bbase  + (size_t)(kb + r) * D_ + sl * 8);
                cpa16(st + doff + ATILE_B,    g_klo  + bbase  + (size_t)(kb + r) * D_ + sl * 8);
                cpa16(st + doff + 2*ATILE_B,  g_vthi + vtbase + (size_t)r * T_ + kb + sl * 8);
                cpa16(st + doff + 3*ATILE_B,  g_vtlo + vtbase + (size_t)r * T_ + kb + sl * 8);
            }
            CP_COMMIT;
        }

        const uint32_t off = (uint32_t)s * ASTAGE_B;

        // S = Q K^T (split-bf16, 3 passes) via ldmatrix
        float sacc[8][4];
        #pragma unroll
        for (int j = 0; j < 8; j++)
            #pragma unroll
            for (int q = 0; q < 4; q++) sacc[j][q] = 0.0f;

        #pragma unroll
        for (int t = 0; t < 4; t++) {
            uint32_t bh4[16], bl4[16];
            #pragma unroll
            for (int jp = 0; jp < 4; jp++) {
                ldsm4(&bh4[jp * 4], kHb + off + (jp * 16 * ASR + t * 16) * 2);
                ldsm4(&bl4[jp * 4], kLb + off + (jp * 16 * ASR + t * 16) * 2);
            }
            #pragma unroll
            for (int j = 0; j < 8; j++) {
                const uint32_t* bhf = &bh4[(j >> 1) * 4 + (j & 1) * 2];
                const uint32_t* blf = &bl4[(j >> 1) * 4 + (j & 1) * 2];
                mma16816(sacc[j], qfh[t], bhf);
                mma16816(sacc[j], qfh[t], blf);
                mma16816(sacc[j], qfl[t], bhf);
            }
        }

        // Causal mask (only tiles crossing the diagonal)
        if (kt * 64 + 63 > qr0) {
            #pragma unroll
            for (int j = 0; j < 8; j++) {
                const int kc = kt * 64 + j * 8 + tg * 2;
                if (kc     > qr0)     sacc[j][0] = -1e30f;
                if (kc + 1 > qr0)     sacc[j][1] = -1e30f;
                if (kc     > qr0 + 8) sacc[j][2] = -1e30f;
                if (kc + 1 > qr0 + 8) sacc[j][3] = -1e30f;
            }
        }

        // Online softmax (2 rows per thread; quad-wide reductions)
        float mx0 = -1e30f, mx1 = -1e30f;
        #pragma unroll
        for (int j = 0; j < 8; j++) {
            mx0 = fmaxf(mx0, fmaxf(sacc[j][0], sacc[j][1]));
            mx1 = fmaxf(mx1, fmaxf(sacc[j][2], sacc[j][3]));
        }
        mx0 = fmaxf(mx0, __shfl_xor_sync(0xffffffffu, mx0, 1));
        mx0 = fmaxf(mx0, __shfl_xor_sync(0xffffffffu, mx0, 2));
        mx1 = fmaxf(mx1, __shfl_xor_sync(0xffffffffu, mx1, 1));
        mx1 = fmaxf(mx1, __shfl_xor_sync(0xffffffffu, mx1, 2));
        const float mn0 = fmaxf(m_i[0], mx0);
        const float mn1 = fmaxf(m_i[1], mx1);
        const float a0 = __expf(m_i[0] - mn0);
        const float a1 = __expf(m_i[1] - mn1);
        m_i[0] = mn0; m_i[1] = mn1;

        float rs0 = 0.0f, rs1 = 0.0f;
        uint32_t pfh[4][4], pfl[4][4];
        #pragma unroll
        for (int j = 0; j < 8; j++) {
            const float p0 = __expf(sacc[j][0] - mn0);
            const float p1 = __expf(sacc[j][1] - mn0);
            const float p2 = __expf(sacc[j][2] - mn1);
            const float p3 = __expf(sacc[j][3] - mn1);
            rs0 += p0 + p1; rs1 += p2 + p3;
            float h0 = __bfloat162float(__float2bfloat16(p0));
            float h1 = __bfloat162float(__float2bfloat16(p1));
            float h2 = __bfloat162float(__float2bfloat16(p2));
            float h3 = __bfloat162float(__float2bfloat16(p3));
            const int t = j >> 1;
            const int o = (j & 1) * 2;
            pfh[t][o + 0] = pack_bf16(h0, h1);
            pfh[t][o + 1] = pack_bf16(h2, h3);
            pfl[t][o + 0] = pack_bf16(p0 - h0, p1 - h1);
            pfl[t][o + 1] = pack_bf16(p2 - h2, p3 - h3);
        }
        rs0 += __shfl_xor_sync(0xffffffffu, rs0, 1);
        rs0 += __shfl_xor_sync(0xffffffffu, rs0, 2);
        rs1 += __shfl_xor_sync(0xffffffffu, rs1, 1);
        rs1 += __shfl_xor_sync(0xffffffffu, rs1, 2);
        l_i[0] = l_i[0] * a0 + rs0;
        l_i[1] = l_i[1] * a1 + rs1;

        #pragma unroll
        for (int j = 0; j < 8; j++) {
            oacc[j][0] *= a0; oacc[j][1] *= a0;
            oacc[j][2] *= a1; oacc[j][3] *= a1;
        }

        // O += P V (split-bf16, 3 passes) via ldmatrix on Vt [d][key]
        #pragma unroll
        for (int t = 0; t < 4; t++) {
            uint32_t bh4[16], bl4[16];
            #pragma unroll
            for (int jp = 0; jp < 4; jp++) {
                ldsm4(&bh4[jp * 4], vHb + off + (jp * 16 * ASR + t * 16) * 2);
                ldsm4(&bl4[jp * 4], vLb + off + (jp * 16 * ASR + t * 16) * 2);
            }
            #pragma unroll
            for (int j = 0; j < 8; j++) {
                const uint32_t* bvh = &bh4[(j >> 1) * 4 + (j & 1) * 2];
                const uint32_t* bvl = &bl4[(j >> 1) * 4 + (j & 1) * 2];
                mma16816(oacc[j], pfh[t], bvh);
                mma16816(oacc[j], pfh[t], bvl);
                mma16816(oacc[j], pfl[t], bvh);
            }
        }
    }

    // Epilogue: normalize; emit split-bf16 into [B,T,C]
    const float inv0 = 1.0f / l_i[0];
    const float inv1 = 1.0f / l_i[1];
    const int b = bh >> 4, h = bh & 15;
    const int trow = qi * 128 + wrow + g;
    #pragma unroll
    for (int j = 0; j < 8; j++) {
        const int d = j * 8 + tg * 2;
        const size_t e0 = ((size_t)(b * T_ + trow)) * C_ + h * 64 + d;
        const size_t e1 = ((size_t)(b * T_ + trow + 8)) * C_ + h * 64 + d;
        float v0 = oacc[j][0] * inv0, v1 = oacc[j][1] * inv0;
        float v2 = oacc[j][2] * inv1, v3 = oacc[j][3] * inv1;
        float h0 = __bfloat162float(__float2bfloat16(v0));
        float h1 = __bfloat162float(__float2bfloat16(v1));
        float h2 = __bfloat162float(__float2bfloat16(v2));
        float h3 = __bfloat162float(__float2bfloat16(v3));
        *(uint32_t*)(g_ahi + e0) = pack_bf16(h0, h1);
        *(uint32_t*)(g_alo + e0) = pack_bf16(v0 - h0, v1 - h1);
        *(uint32_t*)(g_ahi + e1) = pack_bf16(h2, h3);
        *(uint32_t*)(g_alo + e1) = pack_bf16(v2 - h2, v3 - h3);
    }
}

// ---------------------------------------------------------------------------
extern "C" void kernel_launch(void* const* d_in, const int* in_sizes, int n_in,
                              void* d_out, int out_size)
{
    const float* x  = (const float*)d_in[0];
    const float* Wq = (const float*)d_in[1];
    const float* bq = (const float*)d_in[2];
    const float* Wk = (const float*)d_in[3];
    const float* bk = (const float*)d_in[4];
    const float* Wv = (const float*)d_in[5];
    const float* bv = (const float*)d_in[6];
    const float* Wp = (const float*)d_in[7];
    const float* bp = (const float*)d_in[8];
    float* out = (float*)d_out;

    cudaFuncSetAttribute(attn_kernel, cudaFuncAttributeMaxDynamicSharedMemorySize,
                         ATTN_SMEM);
    cudaFuncSetAttribute(gemm_kernel<0>, cudaFuncAttributeMaxDynamicSharedMemorySize,
                         GEMM_SMEM);
    cudaFuncSetAttribute(gemm_kernel<1>, cudaFuncAttributeMaxDynamicSharedMemorySize,
                         GEMM_SMEM);

    // 1) split fp32 -> bf16 hi/lo
    split_kernel<0><<<(M_*C_/8 + 255)/256, 256>>>(x,  M_*C_/8);
    split_kernel<1><<<(C_*C_/8 + 255)/256, 256>>>(Wq, C_*C_/8);
    split_kernel<2><<<(C_*C_/8 + 255)/256, 256>>>(Wk, C_*C_/8);
    split_kernel<3><<<(C_*C_/8 + 255)/256, 256>>>(Wv, C_*C_/8);
    split_kernel<4><<<(C_*C_/8 + 255)/256, 256>>>(Wp, C_*C_/8);

    // 2) QKV projections (tensor cores, split-bf16 outputs)
    gemm_kernel<0><<<dim3(C_/128, M_/128, 3), 256, GEMM_SMEM>>>(bq, bk, bv, nullptr);

    // 3) causal flash attention (tensor cores)
    attn_kernel<<<dim3(T_/128, B_*H_), 256, ATTN_SMEM>>>();

    // 4) output projection (tensor cores)
    gemm_kernel<1><<<dim3(C_/128, M_/128, 1), 256, GEMM_SMEM>>>(bp, nullptr, nullptr, out);
}